// round 12
// baseline (speedup 1.0000x reference)
#include <cuda_runtime.h>

// ---------------- problem constants ----------------
#define BATCH 32
#define TDIM  2048
#define KP    17
#define HID   64
#define NPOS  (TDIM * KP)   // 34816
#define TT    16            // blk0 time tile
#define GR    256           // GEMM rows per chunk
#define CPOS  224           // output positions per chunk (GR - 32 halo)
#define CHUNKS 2
#define NCTA  78            // ceil(34816 / 448)
#define NZ    5
#define LTH   1024

typedef unsigned long long ull;
typedef unsigned int u32;

// ---------------- device scratch ----------------
__device__ float g_bufA[(size_t)BATCH * NPOS * HID];
__device__ float g_bufB[(size_t)BATCH * NPOS * HID];
__device__ float g_M0[9 * 64];            // blk0 folded weights (fp32)
__device__ float g_MTf1[24 * 8 * 64];     // layer1 B, fragment-major tf32
__device__ float g_MTf2[24 * 8 * 64];     // layer2 B
__device__ float2 g_adjD[KP * NZ];        // {w, bitcast((k_e - v)*68)}
__device__ float2 g_adjT0[KP * NZ];       // {w, bitcast(k*3)} for blk0
__device__ float g_part[(size_t)BATCH * 80 * 64];   // pool partials

// ---------------- helpers ----------------
__device__ __forceinline__ ull pack2_dup(float x) {
    ull r; u32 xb = __float_as_uint(x);
    asm("mov.b64 %0, {%1, %1};" : "=l"(r) : "r"(xb));
    return r;
}
__device__ __forceinline__ void fma2(ull& c, ull a, ull b) {
    asm("fma.rn.f32x2 %0, %1, %2, %3;" : "=l"(c) : "l"(a), "l"(b), "l"(c));
}
__device__ __forceinline__ float2 unpack2(ull v) {
    u32 lo, hi;
    asm("mov.b64 {%0, %1}, %2;" : "=r"(lo), "=r"(hi) : "l"(v));
    return make_float2(__uint_as_float(lo), __uint_as_float(hi));
}
__device__ __forceinline__ u32 f2tf(float f) {
    u32 u; asm("cvt.rna.tf32.f32 %0, %1;" : "=r"(u) : "f"(f)); return u;
}
__device__ __forceinline__ float rtf(float f) {   // tf32-rounded float
    return __uint_as_float(f2tf(f));
}
__device__ __forceinline__ u32 smem_u32(const void* p) {
    u32 a;
    asm("{ .reg .u64 t; cvta.to.shared.u64 t, %1; cvt.u32.u64 %0, t; }" : "=r"(a) : "l"(p));
    return a;
}
__device__ __forceinline__ void cpa16(u32 daddr, const void* src) {
    asm volatile("cp.async.cg.shared.global [%0], [%1], 16;" :: "r"(daddr), "l"(src));
}
__device__ __forceinline__ void mma_tf32(float* c, const u32* a, const u32* b) {
    asm volatile(
        "mma.sync.aligned.m16n8k8.row.col.f32.tf32.tf32.f32 "
        "{%0,%1,%2,%3}, {%4,%5,%6,%7}, {%8,%9}, {%0,%1,%2,%3};"
        : "+f"(c[0]), "+f"(c[1]), "+f"(c[2]), "+f"(c[3])
        : "r"(a[0]), "r"(a[1]), "r"(a[2]), "r"(a[3]), "r"(b[0]), "r"(b[1]));
}

// ---------------- weight folding (fragment-major, raw-channel-order k map) ----------------
__global__ void prep_kernel(const float* __restrict__ gw0,
                            const float* __restrict__ gw1,
                            const float* __restrict__ gw2,
                            const float* __restrict__ tcw) {
    int id = blockIdx.x * blockDim.x + threadIdx.x;
    const int n0 = 9 * 64, n1 = 192 * 64;
    if (id >= n0 + 2 * n1) return;
    int blk, cin, e; const float* gw;
    if (id < n0)           { blk = 0; cin = 3;  gw = gw0; e = id; }
    else if (id < n0 + n1) { blk = 1; cin = 64; gw = gw1; e = id - n0; }
    else                   { blk = 2; cin = 64; gw = gw2; e = id - n0 - n1; }
    int km = e / 64, o = e % 64;
    int j = km / cin, c = km % cin;
    const float* tw = tcw + (size_t)blk * HID * HID * 3;
    float s = 0.f;
    for (int h = 0; h < HID; ++h)
        s = fmaf(gw[c * HID + h], tw[(o * HID + h) * 3 + j], s);
    if (blk == 0) { g_M0[km * 64 + o] = s; return; }
    // A slab holds RAW channel order: thread (g,tig) reads channels {2tig, 2tig+1}
    // at k-slots {tig, tig+4}. So B slot for channel c8 = km&7: tig=c8>>1, h=c8&1.
    int s8 = km >> 3, c8 = km & 7;
    int tig = c8 >> 1, h = c8 & 1;
    int i = o >> 3, g = o & 7;
    int slot = ((s8 * 8 + i) * 32 + (g * 4 + tig)) * 2 + h;
    float* MT = (blk == 1) ? g_MTf1 : g_MTf2;
    MT[slot] = __uint_as_float(f2tf(s));
}

__global__ void adjprep_kernel(const float* __restrict__ adj) {
    int v = threadIdx.x;
    if (v >= KP) return;
    int cnt = 0;
    for (int k = 0; k < KP; ++k) {
        float w = adj[k * KP + v];
        if (w != 0.0f && cnt < NZ) {
            g_adjD [v * NZ + cnt] = make_float2(w, __int_as_float((k - v) * 68));
            g_adjT0[v * NZ + cnt] = make_float2(w, __int_as_float(k * 3));
            ++cnt;
        }
    }
    for (; cnt < NZ; ++cnt) {
        g_adjD [v * NZ + cnt] = make_float2(0.0f, __int_as_float(0));
        g_adjT0[v * NZ + cnt] = make_float2(0.0f, __int_as_float(0));
    }
}

// ---------------- block 0 (fp32 FFMA2 path, CIN=3; outputs tf32-rounded) ----------------
__global__ void __launch_bounds__(512) blk0_kernel(
    const float* __restrict__ kpts,
    const float* __restrict__ bns, const float* __restrict__ bnb,
    const float* __restrict__ bnm, const float* __restrict__ bnv,
    float* __restrict__ out)
{
    constexpr int PR = (TT + 2) * KP;   // 306
    __shared__ float  sM0[9 * 64];
    __shared__ ull    sZ[PR * 4];
    __shared__ float  sBN[128];
    __shared__ float2 sT[KP * NZ];

    const int tid = threadIdx.x;
    const int b   = blockIdx.y;
    const int t0  = blockIdx.x * TT;

    for (int i = tid; i < 9 * 64; i += 512) sM0[i] = g_M0[i];
    if (tid < KP * NZ) sT[tid] = g_adjT0[tid];
    if (tid < 64) {
        float inv = __ldg(bns + tid) * rsqrtf(__ldg(bnv + tid) + 1e-5f);
        sBN[tid] = inv;
        sBN[64 + tid] = __ldg(bnb + tid) - __ldg(bnm + tid) * inv;
    }
    __syncthreads();

    for (int idx = tid; idx < PR * 3; idx += 512) {
        int ph = idx / 3, c = idx - ph * 3;
        int h = ph / KP, kk = ph - h * KP;
        int t = t0 - 1 + h;
        float v = 0.f;
        if ((unsigned)t < (unsigned)TDIM) {
            const float* xr = kpts + (size_t)(b * TDIM + t) * (KP * 3);
#pragma unroll
            for (int e = 0; e < NZ; ++e) {
                float2 wt = sT[kk * NZ + e];
                v = fmaf(wt.x, xr[__float_as_int(wt.y) + c], v);
            }
        }
        sZ[ph * 4 + c] = pack2_dup(v);
    }
    __syncthreads();

    const int cg = tid & 7, rt = tid >> 3;
    const int o1 = cg * 4, o2 = 32 + o1;
    const size_t gb = (size_t)(b * TDIM + t0) * KP;
    const float4 invA = *(const float4*)(sBN + o1);
    const float4 invB = *(const float4*)(sBN + o2);
    const float4 betA = *(const float4*)(sBN + 64 + o1);
    const float4 betB = *(const float4*)(sBN + 64 + o2);

    for (int it = 0; it < 2; ++it) {
        bool act = (it == 0) || (tid < 32);
        if (!act) continue;
        const int prow = (it ? 64 + rt : rt);

        ull acc[4][4] = {};
#pragma unroll
        for (int j = 0; j < 3; ++j) {
            const ull* zb = sZ + (prow + j * KP) * 4;
#pragma unroll
            for (int c = 0; c < 3; ++c) {
                const float* mk = sM0 + (j * 3 + c) * 64;
                ulonglong2 m1 = *(const ulonglong2*)(mk + o1);
                ulonglong2 m2 = *(const ulonglong2*)(mk + o2);
#pragma unroll
                for (int i = 0; i < 4; ++i) {
                    ull av = zb[i * 68 * 4 + c];
                    fma2(acc[i][0], av, m1.x); fma2(acc[i][1], av, m1.y);
                    fma2(acc[i][2], av, m2.x); fma2(acc[i][3], av, m2.y);
                }
            }
        }
#pragma unroll
        for (int i = 0; i < 4; ++i) {
            float2 q0 = unpack2(acc[i][0]), q1 = unpack2(acc[i][1]);
            float2 q2 = unpack2(acc[i][2]), q3 = unpack2(acc[i][3]);
            size_t rowo = (gb + prow + 68 * i) * 64;
            float4 v1, v2;
            v1.x = rtf(fmaxf(fmaf(q0.x, invA.x, betA.x), 0.f));
            v1.y = rtf(fmaxf(fmaf(q0.y, invA.y, betA.y), 0.f));
            v1.z = rtf(fmaxf(fmaf(q1.x, invA.z, betA.z), 0.f));
            v1.w = rtf(fmaxf(fmaf(q1.y, invA.w, betA.w), 0.f));
            v2.x = rtf(fmaxf(fmaf(q2.x, invB.x, betB.x), 0.f));
            v2.y = rtf(fmaxf(fmaf(q2.y, invB.y, betB.y), 0.f));
            v2.z = rtf(fmaxf(fmaf(q3.x, invB.z, betB.z), 0.f));
            v2.w = rtf(fmaxf(fmaf(q3.y, invB.w, betB.w), 0.f));
            *(float4*)(out + rowo + o1) = v1;
            *(float4*)(out + rowo + o2) = v2;
        }
    }
}

// ---------------- layers 1 & 2: double-buffered cp.async chunks ----------------
template <int DIL, bool POOL>
__global__ void __launch_bounds__(LTH) layer_kernel(
    const float* __restrict__ Y,
    const float* __restrict__ MTf,
    const float* __restrict__ bns, const float* __restrict__ bnb,
    const float* __restrict__ bnm, const float* __restrict__ bnv,
    float* __restrict__ outp)
{
    constexpr int NSH  = KP * DIL;
    constexpr int RA   = GR + 2 * NSH;      // 290 / 324
    constexpr int ZS   = 68;
    constexpr int SLAB = RA * ZS;
    constexpr int OFF_B   = 2 * SLAB;
    constexpr int OFF_INV = OFF_B + 12288;
    constexpr int OFF_BET = OFF_INV + 64;
    constexpr int OFF_T   = OFF_BET + 64;

    extern __shared__ float sm[];
    u32*    sBf  = (u32*)(sm + OFF_B);
    float*  sInv = sm + OFF_INV;
    float*  sBet = sm + OFF_BET;
    float2* sT   = (float2*)(sm + OFF_T);
    float*  sPl  = sm + OFF_B;               // pool scratch aliases B (used at the very end)

    const int tid = threadIdx.x;
    const int wid = tid >> 5, lid = tid & 31;
    const int g = lid >> 2, tig = lid & 3;
    const int b = blockIdx.y;
    const int p0 = blockIdx.x * (CPOS * CHUNKS);
    const float* Yb = Y + (size_t)b * NPOS * 64;
    const u32 smbase = smem_u32(sm);

    if (tid < KP * NZ) sT[tid] = g_adjD[tid];
    if (tid < 64) {
        float inv = __ldg(bns + tid) * rsqrtf(__ldg(bnv + tid) + 1e-5f);
        sInv[tid] = inv;
        sBet[tid] = __ldg(bnb + tid) - __ldg(bnm + tid) * inv;
    }
    for (int i = tid; i < 3072; i += LTH)
        *(uint4*)(sBf + i * 4) = *(const uint4*)(MTf + i * 4);

    // ---- staging: pure cp.async of pre-rounded tf32 data, raw channel order ----
    auto stage = [&](int bi, int pcbase) {
        const u32 dbase = smbase + (u32)(bi * SLAB) * 4;
        for (int idx = tid; idx < RA * 16; idx += LTH) {
            int zr = idx >> 4, g8 = idx & 15;
            int p = pcbase + zr;
            u32 daddr = dbase + (u32)(zr * ZS + g8 * 4) * 4;
            if ((unsigned)p < (unsigned)NPOS)
                cpa16(daddr, Yb + (size_t)p * 64 + g8 * 4);
            else
                asm volatile("st.shared.v4.b32 [%0], {%1,%1,%1,%1};" :: "r"(daddr), "r"(0));
        }
        asm volatile("cp.async.commit_group;" ::: "memory");
    };

    const int rt = wid >> 1;          // row tile 0..15
    const int ih = wid & 1;           // n-half (channels ih*32 .. ih*32+31)
    const int c4 = tid & 15;
    const float4 inv4 = *(const float4*)(sInv + c4 * 4);
    const float4 bet4 = *(const float4*)(sBet + c4 * 4);
    float ps[4] = {0.f, 0.f, 0.f, 0.f};
    float* ob = outp ? (outp + (size_t)b * NPOS * 64) : nullptr;

    stage(0, p0 - 16 - NSH);
    asm volatile("cp.async.wait_group 0;" ::: "memory");
    __syncthreads();

#pragma unroll
    for (int ch = 0; ch < CHUNKS; ++ch) {
        const int pc = p0 + ch * CPOS;
        if (ch + 1 < CHUNKS)
            stage(ch + 1, pc + CPOS - 16 - NSH);   // overlap with GEMM below

        const u32*  bufc = (const u32*)(sm + ch * SLAB);
        float*      sD   = sm + ch * SLAB;

        // ---- GEMM: warp-pair (rt, ih); 1 m16 tile x 4 n8 cols ----
        float c[4][4];
#pragma unroll
        for (int i = 0; i < 4; ++i)
#pragma unroll
            for (int n = 0; n < 4; ++n) c[i][n] = 0.f;

#pragma unroll
        for (int tap = 0; tap < 3; ++tap) {
            const u32* za = bufc + (rt * 16 + tap * NSH + g) * ZS + 2 * tig;
#pragma unroll
            for (int k8 = 0; k8 < 8; ++k8) {
                const u32* zp = za + k8 * 8;
                u32 a[4];
                { uint2 v = *(const uint2*)zp;             a[0] = v.x; a[2] = v.y; }
                { uint2 v = *(const uint2*)(zp + 8 * ZS);  a[1] = v.x; a[3] = v.y; }
                const u32* bb = sBf + ((tap * 8 + k8) * 8 + ih * 4) * 64 + lid * 2;
#pragma unroll
                for (int i = 0; i < 4; ++i) {
                    uint2 bv = *(const uint2*)(bb + i * 64);
                    u32 bf[2] = {bv.x, bv.y};
                    mma_tf32(c[i], a, bf);
                }
            }
        }
        __syncthreads();   // slab reads done; reuse as D

        // ---- D store: D row d at slab row d, channels ih*32 + 8*i_loc + ... ----
        {
            const int r0 = rt * 16 + g;
#pragma unroll
            for (int i = 0; i < 4; ++i) {
                const int chn = (ih * 4 + i) * 8 + 2 * tig;
                *(float2*)(sD + r0 * ZS + chn)       = make_float2(c[i][0], c[i][1]);
                *(float2*)(sD + (r0 + 8) * ZS + chn) = make_float2(c[i][2], c[i][3]);
            }
        }
        __syncthreads();

        // ---- epilogue: adj-mix + BN + ReLU + residual (+ pool) ----
        int r = tid >> 4;
        int p = pc + r;
        int k = p % KP;
        const float* drow = sD + (r + 16) * ZS + c4 * 4;
        const float* rres = Yb + (size_t)p * 64 + c4 * 4;
        float* wout = ob ? (ob + (size_t)p * 64 + c4 * 4) : nullptr;

#pragma unroll
        for (int it = 0; it < 4; ++it) {
            if (r < CPOS && p < NPOS) {
                const float2* tk = sT + k * NZ;
                float4 s = make_float4(0.f, 0.f, 0.f, 0.f);
#pragma unroll
                for (int e = 0; e < NZ; ++e) {
                    float2 wt = tk[e];
                    const float4 dv = *(const float4*)(drow + __float_as_int(wt.y));
                    s.x = fmaf(wt.x, dv.x, s.x);
                    s.y = fmaf(wt.x, dv.y, s.y);
                    s.z = fmaf(wt.x, dv.z, s.z);
                    s.w = fmaf(wt.x, dv.w, s.w);
                }
                const float4 rs = *(const float4*)rres;
                float4 v;
                v.x = fmaxf(fmaf(s.x, inv4.x, bet4.x), 0.f) + rs.x;
                v.y = fmaxf(fmaf(s.y, inv4.y, bet4.y), 0.f) + rs.y;
                v.z = fmaxf(fmaf(s.z, inv4.z, bet4.z), 0.f) + rs.z;
                v.w = fmaxf(fmaf(s.w, inv4.w, bet4.w), 0.f) + rs.w;
                if (POOL) {
                    ps[0] += v.x; ps[1] += v.y; ps[2] += v.z; ps[3] += v.w;
                } else {
                    v.x = rtf(v.x); v.y = rtf(v.y); v.z = rtf(v.z); v.w = rtf(v.w);
                    *(float4*)wout = v;
                }
            }
            r += 64; p += 64;
            k += 13; if (k >= KP) k -= KP;
            drow += 64 * ZS;
            rres += 64 * 64;
            if (!POOL) wout += 64 * 64;
        }

        if (ch + 1 < CHUNKS) {
            asm volatile("cp.async.wait_group 0;" ::: "memory");
            __syncthreads();
        }
    }

    if (POOL) {
        __syncthreads();   // B reads long done; safe to alias
#pragma unroll
        for (int j = 0; j < 4; ++j)
            ps[j] += __shfl_xor_sync(0xFFFFFFFF, ps[j], 16);
        if (lid < 16)
            *(float4*)(sPl + wid * 64 + lid * 4) = make_float4(ps[0], ps[1], ps[2], ps[3]);
        __syncthreads();
        if (tid < 64) {
            float s = 0.f;
            for (int w = 0; w < 32; ++w)
                s += sPl[w * 64 + tid];
            g_part[((size_t)b * 80 + blockIdx.x) * 64 + tid] = s;
        }
    }
}

// ---------------- head: pool finish + LN + FC ----------------
__global__ void head_kernel(const float* __restrict__ lns, const float* __restrict__ lnb,
                            const float* __restrict__ fw,  const float* __restrict__ fb,
                            float* __restrict__ outp) {
    __shared__ float f[64];
    __shared__ float mu_s, rv_s;
    const int b = blockIdx.x, tid = threadIdx.x;
    float s = 0.f;
    for (int i = 0; i < NCTA; ++i)
        s += g_part[((size_t)b * 80 + i) * 64 + tid];
    float v = s * (1.0f / (float)NPOS);
    f[tid] = v;
    __syncthreads();
    if (tid == 0) {
        float m = 0.f;
        for (int i = 0; i < 64; ++i) m += f[i];
        m *= (1.0f / 64.0f);
        float va = 0.f;
        for (int i = 0; i < 64; ++i) { float d = f[i] - m; va = fmaf(d, d, va); }
        va *= (1.0f / 64.0f);
        mu_s = m; rv_s = rsqrtf(va + 1e-5f);
    }
    __syncthreads();
    float nf = (v - mu_s) * rv_s * lns[tid] + lnb[tid];
    __syncthreads();
    f[tid] = nf;
    __syncthreads();
    if (tid < 10) {
        float o = fb[tid];
        for (int c = 0; c < 64; ++c)
            o = fmaf(f[c], fw[c * 10 + tid], o);
        outp[b * 10 + tid] = o;
    }
}

// ---------------- launch ----------------
extern "C" void kernel_launch(void* const* d_in, const int* in_sizes, int n_in,
                              void* d_out, int out_size) {
    const float* kpts = (const float*)d_in[0];
    const float* adj  = (const float*)d_in[1];
    const float* gw0  = (const float*)d_in[2];
    const float* gw1  = (const float*)d_in[3];
    const float* gw2  = (const float*)d_in[4];
    const float* tcw  = (const float*)d_in[5];
    const float* bns  = (const float*)d_in[6];
    const float* bnb  = (const float*)d_in[7];
    const float* bnm  = (const float*)d_in[8];
    const float* bnv  = (const float*)d_in[9];
    const float* lns  = (const float*)d_in[10];
    const float* lnb  = (const float*)d_in[11];
    const float* fw   = (const float*)d_in[12];
    const float* fb   = (const float*)d_in[13];
    float* outp = (float*)d_out;

    float *bufA, *bufB, *MT1, *MT2;
    cudaGetSymbolAddress((void**)&bufA, g_bufA);
    cudaGetSymbolAddress((void**)&bufB, g_bufB);
    cudaGetSymbolAddress((void**)&MT1, g_MTf1);
    cudaGetSymbolAddress((void**)&MT2, g_MTf2);

    // smem floats: 2 slabs + B 12288 + inv/bet 128 + adjT 176
    const size_t smem1 = (size_t)(2 * 290 * 68 + 12288 + 128 + 176) * 4;  // 208,128 B
    const size_t smem2 = (size_t)(2 * 324 * 68 + 12288 + 128 + 176) * 4;  // 226,624 B
    cudaFuncSetAttribute(layer_kernel<1, false>,
                         cudaFuncAttributeMaxDynamicSharedMemorySize, (int)smem1);
    cudaFuncSetAttribute(layer_kernel<2, true>,
                         cudaFuncAttributeMaxDynamicSharedMemorySize, (int)smem2);

    prep_kernel<<<(9 * 64 + 2 * 192 * 64 + 255) / 256, 256>>>(gw0, gw1, gw2, tcw);
    adjprep_kernel<<<1, 32>>>(adj);

    dim3 g0(TDIM / TT, BATCH);     // 128 x 32
    blk0_kernel<<<g0, 512>>>(kpts, bns, bnb, bnm, bnv, bufA);

    dim3 gl(NCTA, BATCH);          // 78 x 32
    layer_kernel<1, false><<<gl, LTH, smem1>>>(
        bufA, MT1, bns + 64,  bnb + 64,  bnm + 64,  bnv + 64,  bufB);
    layer_kernel<2, true><<<gl, LTH, smem2>>>(
        bufB, MT2, bns + 128, bnb + 128, bnm + 128, bnv + 128, nullptr);

    head_kernel<<<BATCH, 64>>>(lns, lnb, fw, fb, outp);
}

// round 15
// speedup vs baseline: 1.1628x; 1.1628x over previous
#include <cuda_runtime.h>

// ---------------- problem constants ----------------
#define BATCH 32
#define TDIM  2048
#define KP    17
#define HID   64
#define NPOS  (TDIM * KP)   // 34816
#define TT    16            // blk0 time tile
#define CPOS  480           // output positions per layer CTA
#define GR    512           // GEMM rows per CTA
#define NCTA  73
#define NZ    5
#define LTH   1024

typedef unsigned long long ull;
typedef unsigned int u32;

// ---------------- device scratch ----------------
__device__ float g_bufA[(size_t)BATCH * NPOS * HID];
__device__ float g_bufB[(size_t)BATCH * NPOS * HID];
__device__ float g_M0[9 * 64];
__device__ float g_MTf1[24 * 8 * 64];     // layer1 B, fragment-major tf32 (raw-order k map)
__device__ float g_MTf2[24 * 8 * 64];
__device__ float2 g_adjD[KP * NZ];        // {w, bitcast((k_e - v)*68)}
__device__ float2 g_adjT0[KP * NZ];       // {w, bitcast(k*3)} for blk0
__device__ float g_part[(size_t)BATCH * 80 * 64];

// ---------------- helpers ----------------
__device__ __forceinline__ ull pack2_dup(float x) {
    ull r; u32 xb = __float_as_uint(x);
    asm("mov.b64 %0, {%1, %1};" : "=l"(r) : "r"(xb));
    return r;
}
__device__ __forceinline__ void fma2(ull& c, ull a, ull b) {
    asm("fma.rn.f32x2 %0, %1, %2, %3;" : "=l"(c) : "l"(a), "l"(b), "l"(c));
}
__device__ __forceinline__ float2 unpack2(ull v) {
    u32 lo, hi;
    asm("mov.b64 {%0, %1}, %2;" : "=r"(lo), "=r"(hi) : "l"(v));
    return make_float2(__uint_as_float(lo), __uint_as_float(hi));
}
__device__ __forceinline__ u32 f2tf(float f) {
    u32 u; asm("cvt.rna.tf32.f32 %0, %1;" : "=r"(u) : "f"(f)); return u;
}
__device__ __forceinline__ float rtf(float f) {
    return __uint_as_float(f2tf(f));
}
__device__ __forceinline__ u32 smem_u32(const void* p) {
    u32 a;
    asm("{ .reg .u64 t; cvta.to.shared.u64 t, %1; cvt.u32.u64 %0, t; }" : "=r"(a) : "l"(p));
    return a;
}
__device__ __forceinline__ void cpa16(u32 daddr, const void* src) {
    asm volatile("cp.async.cg.shared.global [%0], [%1], 16;" :: "r"(daddr), "l"(src));
}
__device__ __forceinline__ void mma_tf32(float* c, const u32* a, const u32* b) {
    asm volatile(
        "mma.sync.aligned.m16n8k8.row.col.f32.tf32.tf32.f32 "
        "{%0,%1,%2,%3}, {%4,%5,%6,%7}, {%8,%9}, {%0,%1,%2,%3};"
        : "+f"(c[0]), "+f"(c[1]), "+f"(c[2]), "+f"(c[3])
        : "r"(a[0]), "r"(a[1]), "r"(a[2]), "r"(a[3]), "r"(b[0]), "r"(b[1]));
}

// ---------------- weight folding (fragment-major, raw-channel-order k map) ----------------
__global__ void prep_kernel(const float* __restrict__ gw0,
                            const float* __restrict__ gw1,
                            const float* __restrict__ gw2,
                            const float* __restrict__ tcw) {
    int id = blockIdx.x * blockDim.x + threadIdx.x;
    const int n0 = 9 * 64, n1 = 192 * 64;
    if (id >= n0 + 2 * n1) return;
    int blk, cin, e; const float* gw;
    if (id < n0)           { blk = 0; cin = 3;  gw = gw0; e = id; }
    else if (id < n0 + n1) { blk = 1; cin = 64; gw = gw1; e = id - n0; }
    else                   { blk = 2; cin = 64; gw = gw2; e = id - n0 - n1; }
    int km = e / 64, o = e % 64;
    int j = km / cin, c = km % cin;
    const float* tw = tcw + (size_t)blk * HID * HID * 3;
    float s = 0.f;
    for (int h = 0; h < HID; ++h)
        s = fmaf(gw[c * HID + h], tw[(o * HID + h) * 3 + j], s);
    if (blk == 0) { g_M0[km * 64 + o] = s; return; }
    // A slab holds RAW channel order: thread (g,tig) reads channels {2tig, 2tig+1}
    // at k-slots {tig, tig+4}. So B slot for channel c8 = km&7: tig=c8>>1, h=c8&1.
    int s8 = km >> 3, c8 = km & 7;
    int tig = c8 >> 1, h = c8 & 1;
    int i = o >> 3, g = o & 7;
    int slot = ((s8 * 8 + i) * 32 + (g * 4 + tig)) * 2 + h;
    float* MT = (blk == 1) ? g_MTf1 : g_MTf2;
    MT[slot] = __uint_as_float(f2tf(s));
}

__global__ void adjprep_kernel(const float* __restrict__ adj) {
    int v = threadIdx.x;
    if (v >= KP) return;
    int cnt = 0;
    for (int k = 0; k < KP; ++k) {
        float w = adj[k * KP + v];
        if (w != 0.0f && cnt < NZ) {
            g_adjD [v * NZ + cnt] = make_float2(w, __int_as_float((k - v) * 68));
            g_adjT0[v * NZ + cnt] = make_float2(w, __int_as_float(k * 3));
            ++cnt;
        }
    }
    for (; cnt < NZ; ++cnt) {
        g_adjD [v * NZ + cnt] = make_float2(0.0f, __int_as_float(0));
        g_adjT0[v * NZ + cnt] = make_float2(0.0f, __int_as_float(0));
    }
}

// ---------------- block 0 (fp32 FFMA2 path, CIN=3; outputs tf32-rounded) ----------------
__global__ void __launch_bounds__(512) blk0_kernel(
    const float* __restrict__ kpts,
    const float* __restrict__ bns, const float* __restrict__ bnb,
    const float* __restrict__ bnm, const float* __restrict__ bnv,
    float* __restrict__ out)
{
    constexpr int PR = (TT + 2) * KP;   // 306
    __shared__ float  sM0[9 * 64];
    __shared__ ull    sZ[PR * 4];
    __shared__ float  sBN[128];
    __shared__ float2 sT[KP * NZ];

    const int tid = threadIdx.x;
    const int b   = blockIdx.y;
    const int t0  = blockIdx.x * TT;

    for (int i = tid; i < 9 * 64; i += 512) sM0[i] = g_M0[i];
    if (tid < KP * NZ) sT[tid] = g_adjT0[tid];
    if (tid < 64) {
        float inv = __ldg(bns + tid) * rsqrtf(__ldg(bnv + tid) + 1e-5f);
        sBN[tid] = inv;
        sBN[64 + tid] = __ldg(bnb + tid) - __ldg(bnm + tid) * inv;
    }
    __syncthreads();

    for (int idx = tid; idx < PR * 3; idx += 512) {
        int ph = idx / 3, c = idx - ph * 3;
        int h = ph / KP, kk = ph - h * KP;
        int t = t0 - 1 + h;
        float v = 0.f;
        if ((unsigned)t < (unsigned)TDIM) {
            const float* xr = kpts + (size_t)(b * TDIM + t) * (KP * 3);
#pragma unroll
            for (int e = 0; e < NZ; ++e) {
                float2 wt = sT[kk * NZ + e];
                v = fmaf(wt.x, xr[__float_as_int(wt.y) + c], v);
            }
        }
        sZ[ph * 4 + c] = pack2_dup(v);
    }
    __syncthreads();

    const int cg = tid & 7, rt = tid >> 3;
    const int o1 = cg * 4, o2 = 32 + o1;
    const size_t gb = (size_t)(b * TDIM + t0) * KP;
    const float4 invA = *(const float4*)(sBN + o1);
    const float4 invB = *(const float4*)(sBN + o2);
    const float4 betA = *(const float4*)(sBN + 64 + o1);
    const float4 betB = *(const float4*)(sBN + 64 + o2);

    for (int it = 0; it < 2; ++it) {
        bool act = (it == 0) || (tid < 32);
        if (!act) continue;
        const int prow = (it ? 64 + rt : rt);

        ull acc[4][4] = {};
#pragma unroll
        for (int j = 0; j < 3; ++j) {
            const ull* zb = sZ + (prow + j * KP) * 4;
#pragma unroll
            for (int c = 0; c < 3; ++c) {
                const float* mk = sM0 + (j * 3 + c) * 64;
                ulonglong2 m1 = *(const ulonglong2*)(mk + o1);
                ulonglong2 m2 = *(const ulonglong2*)(mk + o2);
#pragma unroll
                for (int i = 0; i < 4; ++i) {
                    ull av = zb[i * 68 * 4 + c];
                    fma2(acc[i][0], av, m1.x); fma2(acc[i][1], av, m1.y);
                    fma2(acc[i][2], av, m2.x); fma2(acc[i][3], av, m2.y);
                }
            }
        }
#pragma unroll
        for (int i = 0; i < 4; ++i) {
            float2 q0 = unpack2(acc[i][0]), q1 = unpack2(acc[i][1]);
            float2 q2 = unpack2(acc[i][2]), q3 = unpack2(acc[i][3]);
            size_t rowo = (gb + prow + 68 * i) * 64;
            float4 v1, v2;
            v1.x = rtf(fmaxf(fmaf(q0.x, invA.x, betA.x), 0.f));
            v1.y = rtf(fmaxf(fmaf(q0.y, invA.y, betA.y), 0.f));
            v1.z = rtf(fmaxf(fmaf(q1.x, invA.z, betA.z), 0.f));
            v1.w = rtf(fmaxf(fmaf(q1.y, invA.w, betA.w), 0.f));
            v2.x = rtf(fmaxf(fmaf(q2.x, invB.x, betB.x), 0.f));
            v2.y = rtf(fmaxf(fmaf(q2.y, invB.y, betB.y), 0.f));
            v2.z = rtf(fmaxf(fmaf(q3.x, invB.z, betB.z), 0.f));
            v2.w = rtf(fmaxf(fmaf(q3.y, invB.w, betB.w), 0.f));
            *(float4*)(out + rowo + o1) = v1;
            *(float4*)(out + rowo + o2) = v2;
        }
    }
}

// ---------------- layers 1 & 2: single slab, cp.async stage, warp-pair GEMM ----------------
// 32 warps; warp = (rt, ih): row-tiles {rt, rt+16}, n-half ih. Full 32-tile coverage.
template <int DIL, bool POOL>
__global__ void __launch_bounds__(LTH) layer_kernel(
    const float* __restrict__ Y,
    const float* __restrict__ MTf,
    const float* __restrict__ bns, const float* __restrict__ bnb,
    const float* __restrict__ bnm, const float* __restrict__ bnv,
    float* __restrict__ outp)
{
    constexpr int NSH = KP * DIL;
    constexpr int RA  = GR + 2 * NSH;       // 546 / 580
    constexpr int ZS  = 68;
    constexpr int OFF_B   = RA * ZS;
    constexpr int OFF_INV = OFF_B + 12288;
    constexpr int OFF_BET = OFF_INV + 64;
    constexpr int OFF_T   = OFF_BET + 64;
    constexpr int OFF_PL  = OFF_T + 176;     // 16B-aligned

    extern __shared__ float sm[];
    u32*    sZu  = (u32*)sm;
    u32*    sBf  = (u32*)(sm + OFF_B);
    float*  sInv = sm + OFF_INV;
    float*  sBet = sm + OFF_BET;
    float2* sT   = (float2*)(sm + OFF_T);
    float*  sPl  = sm + OFF_PL;
    float*  sD   = sm;                       // D buffer aliases slab

    const int tid = threadIdx.x;
    const int wid = tid >> 5, lid = tid & 31;
    const int g = lid >> 2, tig = lid & 3;
    const int b = blockIdx.y;
    const int p0 = blockIdx.x * CPOS;
    const int pbase = p0 - 16 - NSH;
    const float* Yb = Y + (size_t)b * NPOS * 64;
    const u32 smbase = smem_u32(sm);

    if (tid < KP * NZ) sT[tid] = g_adjD[tid];
    if (tid < 64) {
        float inv = __ldg(bns + tid) * rsqrtf(__ldg(bnv + tid) + 1e-5f);
        sInv[tid] = inv;
        sBet[tid] = __ldg(bnb + tid) - __ldg(bnm + tid) * inv;
    }
    for (int i = tid; i < 3072; i += LTH)
        *(uint4*)(sBf + i * 4) = *(const uint4*)(MTf + i * 4);

    // ---- staging: pure cp.async of pre-rounded tf32 data, raw channel order ----
    for (int idx = tid; idx < RA * 16; idx += LTH) {
        int zr = idx >> 4, g8 = idx & 15;
        int p = pbase + zr;
        u32 daddr = smbase + (u32)(zr * ZS + g8 * 4) * 4;
        if ((unsigned)p < (unsigned)NPOS)
            cpa16(daddr, Yb + (size_t)p * 64 + g8 * 4);
        else
            asm volatile("st.shared.v4.b32 [%0], {%1,%1,%1,%1};" :: "r"(daddr), "r"(0));
    }
    asm volatile("cp.async.commit_group;" ::: "memory");
    asm volatile("cp.async.wait_group 0;" ::: "memory");
    __syncthreads();

    // ---- GEMM: warp (rt, ih) computes row-tiles rt and rt+16, n-half ih ----
    const int rt = wid >> 1;
    const int ih = wid & 1;
    float c[2][4][4];
#pragma unroll
    for (int ti = 0; ti < 2; ++ti)
#pragma unroll
        for (int i = 0; i < 4; ++i)
#pragma unroll
            for (int n = 0; n < 4; ++n) c[ti][i][n] = 0.f;

#pragma unroll
    for (int tap = 0; tap < 3; ++tap) {
        const u32* za = sZu + (rt * 16 + tap * NSH + g) * ZS + 2 * tig;
#pragma unroll
        for (int k8 = 0; k8 < 8; ++k8) {
            const u32* zp = za + k8 * 8;
            u32 a0[4], a1[4];
            { uint2 v = *(const uint2*)zp;                  a0[0] = v.x; a0[2] = v.y; }
            { uint2 v = *(const uint2*)(zp + 8 * ZS);       a0[1] = v.x; a0[3] = v.y; }
            { uint2 v = *(const uint2*)(zp + 256 * ZS);     a1[0] = v.x; a1[2] = v.y; }
            { uint2 v = *(const uint2*)(zp + 264 * ZS);     a1[1] = v.x; a1[3] = v.y; }
            const u32* bb = sBf + ((tap * 8 + k8) * 8 + ih * 4) * 64 + lid * 2;
#pragma unroll
            for (int i = 0; i < 4; ++i) {
                uint2 bv = *(const uint2*)(bb + i * 64);
                u32 bf[2] = {bv.x, bv.y};
                mma_tf32(c[0][i], a0, bf);
                mma_tf32(c[1][i], a1, bf);
            }
        }
    }
    __syncthreads();   // slab reads done; reuse as D

    // ---- D store: tiles rt (rows rt*16..) and rt+16 (rows rt*16+256..) ----
#pragma unroll
    for (int ti = 0; ti < 2; ++ti) {
        const int r0 = rt * 16 + ti * 256 + g;
#pragma unroll
        for (int i = 0; i < 4; ++i) {
            const int chn = (ih * 4 + i) * 8 + 2 * tig;
            *(float2*)(sD + r0 * ZS + chn)       = make_float2(c[ti][i][0], c[ti][i][1]);
            *(float2*)(sD + (r0 + 8) * ZS + chn) = make_float2(c[ti][i][2], c[ti][i][3]);
        }
    }
    __syncthreads();

    // ---- epilogue: adj-mix + BN + ReLU + residual (+ pool) ----
    const int c4 = tid & 15;
    const float4 inv4 = *(const float4*)(sInv + c4 * 4);
    const float4 bet4 = *(const float4*)(sBet + c4 * 4);
    float ps[4] = {0.f, 0.f, 0.f, 0.f};
    float* ob = outp ? (outp + (size_t)b * NPOS * 64) : nullptr;

    int r = tid >> 4;
    int p = p0 + r;
    int k = p % KP;
    const float* drow = sD + (r + 16) * ZS + c4 * 4;
    const float* rres = Yb + (size_t)p * 64 + c4 * 4;
    float* wout = ob ? (ob + (size_t)p * 64 + c4 * 4) : nullptr;

#pragma unroll 2
    for (int it = 0; it < 8; ++it) {
        if (r < CPOS && p < NPOS) {
            const float2* tk = sT + k * NZ;
            float4 s = make_float4(0.f, 0.f, 0.f, 0.f);
#pragma unroll
            for (int e = 0; e < NZ; ++e) {
                float2 wt = tk[e];
                const float4 dv = *(const float4*)(drow + __float_as_int(wt.y));
                s.x = fmaf(wt.x, dv.x, s.x);
                s.y = fmaf(wt.x, dv.y, s.y);
                s.z = fmaf(wt.x, dv.z, s.z);
                s.w = fmaf(wt.x, dv.w, s.w);
            }
            const float4 rs = *(const float4*)rres;
            float4 v;
            v.x = fmaxf(fmaf(s.x, inv4.x, bet4.x), 0.f) + rs.x;
            v.y = fmaxf(fmaf(s.y, inv4.y, bet4.y), 0.f) + rs.y;
            v.z = fmaxf(fmaf(s.z, inv4.z, bet4.z), 0.f) + rs.z;
            v.w = fmaxf(fmaf(s.w, inv4.w, bet4.w), 0.f) + rs.w;
            if (POOL) {
                ps[0] += v.x; ps[1] += v.y; ps[2] += v.z; ps[3] += v.w;
            } else {
                v.x = rtf(v.x); v.y = rtf(v.y); v.z = rtf(v.z); v.w = rtf(v.w);
                *(float4*)wout = v;
            }
        }
        r += 64; p += 64;
        k += 13; if (k >= KP) k -= KP;
        drow += 64 * ZS;
        rres += 64 * 64;
        if (!POOL) wout += 64 * 64;
    }

    if (POOL) {
#pragma unroll
        for (int j = 0; j < 4; ++j)
            ps[j] += __shfl_xor_sync(0xFFFFFFFF, ps[j], 16);
        if (lid < 16)
            *(float4*)(sPl + wid * 64 + lid * 4) = make_float4(ps[0], ps[1], ps[2], ps[3]);
        __syncthreads();
        if (tid < 64) {
            float s = 0.f;
            for (int w = 0; w < 32; ++w)
                s += sPl[w * 64 + tid];
            g_part[((size_t)b * 80 + blockIdx.x) * 64 + tid] = s;
        }
    }
}

// ---------------- head: pool finish + LN + FC ----------------
__global__ void head_kernel(const float* __restrict__ lns, const float* __restrict__ lnb,
                            const float* __restrict__ fw,  const float* __restrict__ fb,
                            float* __restrict__ outp) {
    __shared__ float f[64];
    __shared__ float mu_s, rv_s;
    const int b = blockIdx.x, tid = threadIdx.x;
    float s = 0.f;
    for (int i = 0; i < NCTA; ++i)
        s += g_part[((size_t)b * 80 + i) * 64 + tid];
    float v = s * (1.0f / (float)NPOS);
    f[tid] = v;
    __syncthreads();
    if (tid == 0) {
        float m = 0.f;
        for (int i = 0; i < 64; ++i) m += f[i];
        m *= (1.0f / 64.0f);
        float va = 0.f;
        for (int i = 0; i < 64; ++i) { float d = f[i] - m; va = fmaf(d, d, va); }
        va *= (1.0f / 64.0f);
        mu_s = m; rv_s = rsqrtf(va + 1e-5f);
    }
    __syncthreads();
    float nf = (v - mu_s) * rv_s * lns[tid] + lnb[tid];
    __syncthreads();
    f[tid] = nf;
    __syncthreads();
    if (tid < 10) {
        float o = fb[tid];
        for (int c = 0; c < 64; ++c)
            o = fmaf(f[c], fw[c * 10 + tid], o);
        outp[b * 10 + tid] = o;
    }
}

// ---------------- launch ----------------
extern "C" void kernel_launch(void* const* d_in, const int* in_sizes, int n_in,
                              void* d_out, int out_size) {
    const float* kpts = (const float*)d_in[0];
    const float* adj  = (const float*)d_in[1];
    const float* gw0  = (const float*)d_in[2];
    const float* gw1  = (const float*)d_in[3];
    const float* gw2  = (const float*)d_in[4];
    const float* tcw  = (const float*)d_in[5];
    const float* bns  = (const float*)d_in[6];
    const float* bnb  = (const float*)d_in[7];
    const float* bnm  = (const float*)d_in[8];
    const float* bnv  = (const float*)d_in[9];
    const float* lns  = (const float*)d_in[10];
    const float* lnb  = (const float*)d_in[11];
    const float* fw   = (const float*)d_in[12];
    const float* fb   = (const float*)d_in[13];
    float* outp = (float*)d_out;

    float *bufA, *bufB, *MT1, *MT2;
    cudaGetSymbolAddress((void**)&bufA, g_bufA);
    cudaGetSymbolAddress((void**)&bufB, g_bufB);
    cudaGetSymbolAddress((void**)&MT1, g_MTf1);
    cudaGetSymbolAddress((void**)&MT2, g_MTf2);

    // smem floats: slab RA*68 + B 12288 + inv/bet 128 + adjT pad 176 + pool 2048
    const size_t smem1 = (size_t)(546 * 68 + 12288 + 128 + 176 + 2048) * 4;  // 207,072 B
    const size_t smem2 = (size_t)(580 * 68 + 12288 + 128 + 176 + 2048) * 4;  // 216,320 B
    cudaFuncSetAttribute(layer_kernel<1, false>,
                         cudaFuncAttributeMaxDynamicSharedMemorySize, (int)smem1);
    cudaFuncSetAttribute(layer_kernel<2, true>,
                         cudaFuncAttributeMaxDynamicSharedMemorySize, (int)smem2);

    prep_kernel<<<(9 * 64 + 2 * 192 * 64 + 255) / 256, 256>>>(gw0, gw1, gw2, tcw);
    adjprep_kernel<<<1, 32>>>(adj);

    dim3 g0(TDIM / TT, BATCH);     // 128 x 32
    blk0_kernel<<<g0, 512>>>(kpts, bns, bnb, bnm, bnv, bufA);

    dim3 gl(NCTA, BATCH);          // 73 x 32
    layer_kernel<1, false><<<gl, LTH, smem1>>>(
        bufA, MT1, bns + 64,  bnb + 64,  bnm + 64,  bnv + 64,  bufB);
    layer_kernel<2, true><<<gl, LTH, smem2>>>(
        bufB, MT2, bns + 128, bnb + 128, bnm + 128, bnv + 128, nullptr);

    head_kernel<<<BATCH, 64>>>(lns, lnb, fw, fb, outp);
}